// round 16
// baseline (speedup 1.0000x reference)
#include <cuda_runtime.h>
#include <cuda_bf16.h>
#include <math.h>
#include <stdint.h>

#define BB 8
#define CC 64
#define OO 64
#define HH 128
#define WW 128
#define HWSZ (HH * WW)

#define TX 16
#define TY 8
#define NOUT 128            // outputs per CTA
#define HX 18
#define HY 10
#define NPOS 180            // real halo positions
#define MPOS 192            // padded to 12 m-tiles of 16
#define NTHR 384            // 12 warps
#define LDP 68              // words per P row
#define LDB 68
#define LDZ 196             // floats per zs row

// smem byte offsets
#define P_B   0                         // packed A: [192 pos][68 w] (hi|lo<<16)
#define B1_B  (P_B + MPOS * LDP * 4)    // 52224: (Wh|Wh) [64 o][68 w]
#define B2_B  (B1_B + OO * LDB * 4)     // 69632: (Wl|Wl)
#define DS_B  (B2_B + OO * LDB * 4)     // 87040: div partials [384]
#define MK_B  (DS_B + NTHR * 4)         // 88576: mask [128]
#define SMEM_BYTES (MK_B + NOUT * 4)    // 89088

__device__ __forceinline__ float bf_hi(uint32_t w) {
    return __uint_as_float(w << 16);
}

__device__ __forceinline__ uint32_t smem_u32(const void* p) {
    uint32_t a;
    asm("{ .reg .u64 t; cvta.to.shared.u64 t, %1; cvt.u32.u64 %0, t; }"
        : "=r"(a) : "l"(p));
    return a;
}

__device__ __forceinline__ void ldsm4(uint32_t& r0, uint32_t& r1,
                                      uint32_t& r2, uint32_t& r3,
                                      uint32_t addr) {
    asm volatile("ldmatrix.sync.aligned.m8n8.x4.shared.b16 {%0,%1,%2,%3}, [%4];"
                 : "=r"(r0), "=r"(r1), "=r"(r2), "=r"(r3) : "r"(addr));
}

__device__ __forceinline__ void mma_bf16(float* c, uint32_t a0, uint32_t a1,
                                         uint32_t a2, uint32_t a3,
                                         uint32_t b0, uint32_t b1) {
    asm volatile(
        "mma.sync.aligned.m16n8k16.row.col.f32.bf16.bf16.f32 "
        "{%0,%1,%2,%3}, {%4,%5,%6,%7}, {%8,%9}, {%0,%1,%2,%3};"
        : "+f"(c[0]), "+f"(c[1]), "+f"(c[2]), "+f"(c[3])
        : "r"(a0), "r"(a1), "r"(a2), "r"(a3), "r"(b0), "r"(b1));
}

__global__ __launch_bounds__(NTHR, 2)
void spconv_mma6_kernel(const float* __restrict__ x,
                        const float* __restrict__ core,
                        const float* __restrict__ periphery,
                        const float* __restrict__ threshold,
                        const float* __restrict__ scale,
                        float* __restrict__ out) {
    extern __shared__ char smem[];
    uint32_t* Pw  = (uint32_t*)(smem + P_B);
    uint32_t* B1w = (uint32_t*)(smem + B1_B);
    uint32_t* B2w = (uint32_t*)(smem + B2_B);
    float* dsum   = (float*)(smem + DS_B);
    float* msk    = (float*)(smem + MK_B);

    const int tid = threadIdx.x;
    const int wid = tid >> 5;
    const int lid = tid & 31;
    const int b   = blockIdx.z;
    const int bx0 = blockIdx.x * TX;
    const int by0 = blockIdx.y * TY;

    // --- stage W: B1 = (Wh|Wh), B2 = (Wl|Wl) ---
    for (int i = tid; i < OO * CC; i += NTHR) {
        int o = i >> 6, c = i & 63;
        float v = core[i];
        __nv_bfloat16 h = __float2bfloat16(v);
        uint32_t hb = (uint32_t)__bfloat16_as_ushort(h);
        __nv_bfloat16 l = __float2bfloat16(v - __bfloat162float(h));
        uint32_t lb = (uint32_t)__bfloat16_as_ushort(l);
        B1w[o * LDB + c] = hb | (hb << 16);
        B2w[o * LDB + c] = lb | (lb << 16);
    }

    // --- stage x halo -> packed P[p][c]: thread owns ONE position, 32 c's ---
    {
        const int cg = tid / MPOS;           // 0,1
        const int p  = tid - cg * MPOS;      // 0..191
        const int iy = p / HX;
        const int ix = p - iy * HX;
        const int gy = by0 + iy - 1;
        const int gx = bx0 + ix - 1;
        const bool inb = (p < NPOS) && ((unsigned)gy < HH) && ((unsigned)gx < WW);
        const int c0 = cg * 32;
        const float* xp = x + (size_t)b * CC * HWSZ + (size_t)c0 * HWSZ
                            + (size_t)gy * WW + gx;
        uint32_t* prow = Pw + p * LDP + c0;
#pragma unroll 4
        for (int j = 0; j < 32; j++) {
            float v = inb ? xp[(size_t)j * HWSZ] : 0.0f;
            __nv_bfloat16 h = __float2bfloat16(v);
            uint32_t hb = (uint32_t)__bfloat16_as_ushort(h);
            __nv_bfloat16 l = __float2bfloat16(v - __bfloat162float(h));
            uint32_t lb = (uint32_t)__bfloat16_as_ushort(l);
            prow[j] = hb | (lb << 16);
        }
    }
    __syncthreads();

    // --- tensor GEMM: warp = 2 m-tiles x 4 n-tiles ---
    const int mp = wid >> 1;
    const int nh = wid & 1;
    const int mbase = mp * 32;

    float Cacc[2][4][4];
#pragma unroll
    for (int mt = 0; mt < 2; mt++)
#pragma unroll
        for (int j = 0; j < 4; j++)
#pragma unroll
            for (int v = 0; v < 4; v++) Cacc[mt][j][v] = 0.0f;

    const uint32_t sb = smem_u32(smem);
    const int arow = mbase + (lid & 15);
    const int acol = (lid >> 4) * 4;
    uint32_t aptr0 = sb + P_B + (uint32_t)(arow * LDP + acol) * 4;
    uint32_t aptr1 = aptr0 + 16 * LDP * 4;
    const int brow = nh * 32 + (lid & 7);
    const int bcol = ((lid >> 3) & 1) * 4;
    uint32_t bptr = sb + ((lid >> 4) ? B2_B : B1_B)
                  + (uint32_t)(brow * LDB + bcol) * 4;

#pragma unroll
    for (int kt = 0; kt < 8; kt++) {
        uint32_t a0, a1, a2, a3, a4, a5, a6, a7;
        ldsm4(a0, a1, a2, a3, aptr0);
        ldsm4(a4, a5, a6, a7, aptr1);
        uint32_t bp = bptr;
#pragma unroll
        for (int j = 0; j < 4; j++) {
            uint32_t b0, b1, d0, d1;
            ldsm4(b0, b1, d0, d1, bp);
            mma_bf16(Cacc[0][j], a0, a1, a2, a3, b0, b1);
            mma_bf16(Cacc[0][j], a0, a1, a2, a3, d0, d1);
            mma_bf16(Cacc[1][j], a4, a5, a6, a7, b0, b1);
            mma_bf16(Cacc[1][j], a4, a5, a6, a7, d0, d1);
            bp += 8 * LDB * 4;
        }
        aptr0 += 32; aptr1 += 32; bptr += 32;
    }

    // --- div from P (hi halves): 3 c-blocks x 128 positions,
    //     4 independent accumulators to break the FFMA chain ---
    {
        const int p   = tid & 127;
        const int blk = tid >> 7;
        const int tx  = p & 15;
        const int ty  = p >> 4;
        const int q0  = (ty + 1) * HX + (tx + 1);
        const int cw0 = (blk == 0) ? 0 : (blk == 1 ? 6 : 11);
        const int cw1 = (blk == 0) ? 6 : (blk == 1 ? 11 : 16);
        float dv0 = 0.0f, dv1 = 0.0f, dv2 = 0.0f, dv3 = 0.0f;
        for (int cw = cw0; cw < cw1; cw++) {
            uint4 cc = *(const uint4*)(Pw + q0 * LDP + cw * 4);
            float c0 = bf_hi(cc.x), c1 = bf_hi(cc.y),
                  c2 = bf_hi(cc.z), c3 = bf_hi(cc.w);
            const int offs[8] = {-HX - 1, -HX, -HX + 1, -1, 1, HX - 1, HX, HX + 1};
#pragma unroll
            for (int k = 0; k < 8; k++) {
                uint4 tt = *(const uint4*)(Pw + (q0 + offs[k]) * LDP + cw * 4);
                float d;
                d = bf_hi(tt.x) - c0; dv0 = fmaf(d, d, dv0);
                d = bf_hi(tt.y) - c1; dv1 = fmaf(d, d, dv1);
                d = bf_hi(tt.z) - c2; dv2 = fmaf(d, d, dv2);
                d = bf_hi(tt.w) - c3; dv3 = fmaf(d, d, dv3);
            }
        }
        dsum[tid] = (dv0 + dv1) + (dv2 + dv3);
    }
    __syncthreads();   // all P reads done

    // --- write z (fp32) over the P region: zs[o][LDZ] ---
    float* zs = (float*)smem;
    {
        const int g = lid >> 2;
        const int t = lid & 3;
#pragma unroll
        for (int mt = 0; mt < 2; mt++) {
            const int pos = mbase + mt * 16 + g;
#pragma unroll
            for (int j = 0; j < 4; j++) {
                const int o0 = nh * 32 + j * 8 + 2 * t;
                zs[o0 * LDZ + pos]           = Cacc[mt][j][0];
                zs[(o0 + 1) * LDZ + pos]     = Cacc[mt][j][1];
                zs[o0 * LDZ + pos + 8]       = Cacc[mt][j][2];
                zs[(o0 + 1) * LDZ + pos + 8] = Cacc[mt][j][3];
            }
        }
    }

    // --- mask ---
    if (tid < NOUT) {
        float dv = dsum[tid] + dsum[tid + NOUT] + dsum[tid + 2 * NOUT];
        float tt = (dv - threshold[0]) * scale[0];
        float sg = 1.0f / (1.0f + __expf(-tt));
        msk[tid] = (sg > 0.5f) ? 1.0f : 0.0f;
    }
    __syncthreads();

    // --- vectorized periphery conv + masked select: 4 outputs/thread/iter ---
    const float pr0 = periphery[0], pr1 = periphery[1], pr2 = periphery[2],
                pr3 = periphery[3], pr4 = periphery[4], pr5 = periphery[5],
                pr6 = periphery[6], pr7 = periphery[7];
    float* ob = out + (size_t)b * OO * HWSZ;

    for (int i = tid; i < OO * NOUT / 4; i += NTHR) {
        const int o   = i >> 5;
        const int pg  = i & 31;
        const int ty  = pg >> 2;
        const int tx0 = (pg & 3) * 4;
        const float* zo = zs + o * LDZ;

        const int rb = ty * HX + tx0;
        float2 t01 = *(const float2*)(zo + rb);
        float2 t23 = *(const float2*)(zo + rb + 2);
        float2 t45 = *(const float2*)(zo + rb + 4);
        float2 m01 = *(const float2*)(zo + rb + HX);
        float2 m23 = *(const float2*)(zo + rb + HX + 2);
        float2 m45 = *(const float2*)(zo + rb + HX + 4);
        float2 b01 = *(const float2*)(zo + rb + 2 * HX);
        float2 b23 = *(const float2*)(zo + rb + 2 * HX + 2);
        float2 b45 = *(const float2*)(zo + rb + 2 * HX + 4);

        const float tv[6] = {t01.x, t01.y, t23.x, t23.y, t45.x, t45.y};
        const float mv[6] = {m01.x, m01.y, m23.x, m23.y, m45.x, m45.y};
        const float bv[6] = {b01.x, b01.y, b23.x, b23.y, b45.x, b45.y};

        float4 mk4 = *(const float4*)(msk + ty * TX + tx0);
        const float mks[4] = {mk4.x, mk4.y, mk4.z, mk4.w};

        float4 res;
        float* rp = (float*)&res;
#pragma unroll
        for (int j = 0; j < 4; j++) {
            float a;
            a = pr0 * tv[j];
            a = fmaf(pr1, tv[j + 1], a);
            a = fmaf(pr2, tv[j + 2], a);
            a = fmaf(pr3, mv[j], a);
            a = fmaf(pr4, mv[j + 2], a);
            a = fmaf(pr5, bv[j], a);
            a = fmaf(pr6, bv[j + 1], a);
            a = fmaf(pr7, bv[j + 2], a);
            rp[j] = (mks[j] > 0.5f) ? a : mv[j + 1];
        }
        __stcg((float4*)&ob[(size_t)o * HWSZ + (size_t)(by0 + ty) * WW + bx0 + tx0],
               res);
    }
}

extern "C" void kernel_launch(void* const* d_in, const int* in_sizes, int n_in,
                              void* d_out, int out_size) {
    const float* x    = (const float*)d_in[0];
    const float* core = (const float*)d_in[1];
    const float* peri = (const float*)d_in[2];
    const float* thr  = (const float*)d_in[3];
    const float* scl  = (const float*)d_in[4];
    float* out = (float*)d_out;

    cudaFuncSetAttribute(spconv_mma6_kernel,
                         cudaFuncAttributeMaxDynamicSharedMemorySize, SMEM_BYTES);

    dim3 grid(WW / TX, HH / TY, BB);   // 1024 CTAs
    spconv_mma6_kernel<<<grid, NTHR, SMEM_BYTES>>>(x, core, peri, thr, scl, out);
}